// round 8
// baseline (speedup 1.0000x reference)
#include <cuda_runtime.h>
#include <cuda_fp16.h>
#include <cuda_fp8.h>
#include <math.h>

// Problem constants (fixed by the reference)
#define NROWS 25088     // B*H*W
#define DIM   64
#define KNEG  100
#define HW    3136      // H*W
#define DHW   200704    // D*H*W
#define NBLK  (NROWS / 8)   // 3136 neg-kernel blocks
#define FXSCALE 274877906944.0f   // 2^38 fixed-point scale

// Scratch (no cudaMalloc allowed)
__device__ unsigned char      g_x1q[NROWS * DIM];  // normalized x1, fp8 e4m3, 1.6MB
__device__ float              g_pos[NROWS];
__device__ unsigned long long g_acc = 0;           // fixed-point loss accumulator
__device__ unsigned int       g_cnt = 0;           // finished-block counter

// ---------------------------------------------------------------------------
// Kernel A (round-4 proven): Block = 256 threads = 8 warps handles 32 rows.
// Warp w owns dims [8w, 8w+8) for all 32 rows; lane = row-within-block.
// Every global load is one 128B warp transaction. Cross-warp reductions via
// smem. 32 | 3136 so a block never straddles a batch boundary.
// ---------------------------------------------------------------------------
__global__ void normalize_kernel(const float* __restrict__ x1,
                                 const float* __restrict__ x2) {
    __shared__ float s1s[8][32];
    __shared__ float s2s[8][32];
    __shared__ float pss[8][32];

    int lane = threadIdx.x & 31;   // row within block
    int part = threadIdx.x >> 5;   // dim chunk (warp id)
    int n = blockIdx.x * 32 + lane;
    int b  = n / HW;
    int hw = n - b * HW;
    const float* p1 = x1 + (size_t)b * DHW + (size_t)(part * 8) * HW + hw;
    const float* p2 = x2 + (size_t)b * DHW + (size_t)(part * 8) * HW + hw;

    float v1[8], v2[8];
    #pragma unroll
    for (int i = 0; i < 8; i++) v1[i] = p1[i * HW];
    #pragma unroll
    for (int i = 0; i < 8; i++) v2[i] = p2[i * HW];

    float s1 = 0.f, s2 = 0.f;
    #pragma unroll
    for (int i = 0; i < 8; i++) {
        s1 = fmaf(v1[i], v1[i], s1);
        s2 = fmaf(v2[i], v2[i], s2);
    }
    s1s[part][lane] = s1;
    s2s[part][lane] = s2;
    __syncthreads();

    float t1 = 0.f, t2 = 0.f;
    #pragma unroll
    for (int p = 0; p < 8; p++) { t1 += s1s[p][lane]; t2 += s2s[p][lane]; }
    float sc1 = 1.0f / fmaxf(sqrtf(t1), 1e-12f);
    float sc2 = 1.0f / fmaxf(sqrtf(t2), 1e-12f);

    float pos = 0.f;
    __nv_fp8x2_storage_t qv[4];
    #pragma unroll
    for (int i = 0; i < 4; i++) {
        float a0 = v1[2*i]   * sc1;
        float a1 = v1[2*i+1] * sc1;
        pos += __expf(a0 * (v2[2*i]   * sc2));
        pos += __expf(a1 * (v2[2*i+1] * sc2));
        float2 f2; f2.x = a0; f2.y = a1;
        qv[i] = __nv_cvt_float2_to_fp8x2(f2, __NV_SATFINITE, __NV_E4M3);
    }
    *(uint2*)(g_x1q + (size_t)n * DIM + part * 8) = *(const uint2*)qv;

    pss[part][lane] = pos;
    __syncthreads();
    if (part == 0) {
        float pt = 0.f;
        #pragma unroll
        for (int p = 0; p < 8; p++) pt += pss[p][lane];
        g_pos[n] = pt;
    }
}

// ---------------------------------------------------------------------------
// Kernel B (round-4 proven body + fused finalize): negatives over the fp8
// table. One warp per row; 8 groups of 4 lanes, each group one k per
// iteration; lane loads uint4 (16 fp8). Block reduces its 8 row losses,
// quantizes to u64 fixed point (2^38), atomically accumulates. The last
// block to finish converts to the mean, writes d_out, and resets the
// accumulator/counter for the next graph replay. Integer atomics make the
// result bit-deterministic regardless of block completion order.
// ---------------------------------------------------------------------------
__global__ void neg_kernel(const int* __restrict__ neg_idx,
                           float* __restrict__ out) {
    __shared__ int   sidx[8][KNEG];
    __shared__ float lsum[8];
    int warp = threadIdx.x >> 5;
    int lane = threadIdx.x & 31;
    int n = blockIdx.x * 8 + warp;

    for (int k = lane; k < KNEG; k += 32)
        sidx[warp][k] = neg_idx[(size_t)n * KNEG + k];
    __syncwarp();

    int grp = lane >> 2;  // which of 8 concurrent k's
    int sub = lane & 3;   // 16-dim chunk

    // query chunk: 16 fp8 -> 8 half2 in registers
    uint4 qraw = ((const uint4*)(g_x1q + (size_t)n * DIM))[sub];
    __half2 q[8];
    {
        const __nv_fp8x2_storage_t* qs = (const __nv_fp8x2_storage_t*)&qraw;
        #pragma unroll
        for (int i = 0; i < 8; i++) {
            __half2_raw hr = __nv_cvt_fp8x2_to_halfraw2(qs[i], __NV_E4M3);
            q[i] = *(__half2*)&hr;
        }
    }

    float negacc = 0.f;
    #pragma unroll
    for (int it = 0; it < 13; it++) {
        int k = it * 8 + grp;
        bool valid = (k < KNEG);
        int j = sidx[warp][valid ? k : (KNEG - 1)];
        uint4 bv = ((const uint4*)(g_x1q + (size_t)j * DIM))[sub];
        const __nv_fp8x2_storage_t* bs = (const __nv_fp8x2_storage_t*)&bv;
        __half2 acc = __floats2half2_rn(0.f, 0.f);
        #pragma unroll
        for (int i = 0; i < 8; i++) {
            __half2_raw hr = __nv_cvt_fp8x2_to_halfraw2(bs[i], __NV_E4M3);
            acc = __hfma2(q[i], *(__half2*)&hr, acc);
        }
        float2 f = __half22float2(acc);
        float p = f.x + f.y;
        p += __shfl_xor_sync(0xffffffffu, p, 2);
        p += __shfl_xor_sync(0xffffffffu, p, 1);
        float e = __expf(p);
        negacc += valid ? e : 0.f;
    }
    negacc += __shfl_xor_sync(0xffffffffu, negacc, 4);
    negacc += __shfl_xor_sync(0xffffffffu, negacc, 8);
    negacc += __shfl_xor_sync(0xffffffffu, negacc, 16);

    if (lane == 0) {
        float pos = g_pos[n];
        lsum[warp] = logf(pos + negacc) - logf(pos);   // always > 0
    }
    __syncthreads();

    if (threadIdx.x == 0) {
        float s = 0.f;
        #pragma unroll
        for (int w = 0; w < 8; w++) s += lsum[w];
        atomicAdd(&g_acc, (unsigned long long)(s * FXSCALE));
        __threadfence();
        unsigned int ticket = atomicAdd(&g_cnt, 1u);
        if (ticket == NBLK - 1) {
            unsigned long long tot = atomicExch(&g_acc, 0ULL);  // read + reset
            out[0] = (float)((double)tot / (double)FXSCALE / (double)NROWS);
            atomicExch(&g_cnt, 0u);                             // reset for replay
        }
    }
}

extern "C" void kernel_launch(void* const* d_in, const int* in_sizes, int n_in,
                              void* d_out, int out_size) {
    const float* x1      = (const float*)d_in[0];
    const float* x2      = (const float*)d_in[1];
    const int*   neg_idx = (const int*)  d_in[2];
    float*       out     = (float*)d_out;

    normalize_kernel<<<NROWS / 32, 256>>>(x1, x2);
    neg_kernel<<<NBLK, 256>>>(neg_idx, out);
}